// round 7
// baseline (speedup 1.0000x reference)
#include <cuda_runtime.h>
#include <cuda_fp16.h>
#include <math.h>
#include <cstdint>

// Problem constants (fixed by the reference)
#define GM 50000        // nodes
#define GK 3703         // input dim
#define GKP 3712        // padded K (multiple of 32; rows 16B aligned in fp16)
#define GN 256          // hidden dim
#define GE 400000       // edges
#define GO 6            // output classes

#define BK 32           // K per chunk (fp16)
#define NCH (GKP / BK)  // 116
#define ROWB 80         // padded smem row stride in bytes (32 halves -> 40 halves)
#define STAGE_BYTES 20480   // A(128*80) + B(128*80)
#define NSTAGE 3

// ---------------- scratch (static device memory; no allocation) ----------------
__device__ __align__(16) float  g_support1[(size_t)GM * GN];  // X @ W1    (51.2 MB)
__device__ __align__(16) float  g_support2[(size_t)GM * GO];  // h1 @ W2   (1.2 MB)
__device__ __align__(16) __half g_Xh[(size_t)GM * GKP];       // fp16 X, padded (371 MB)
__device__ __align__(16) __half g_W1th[(size_t)GN * GKP];     // fp16 W1^T, padded (1.9 MB)
__device__ int   g_deg[GM];
__device__ int   g_cur[GM];
__device__ int   g_off[GM + 1];
__device__ int   g_ssrc[GE];
__device__ float g_sw[GE];

// ---------------- ptx helpers ----------------
__device__ __forceinline__ uint32_t smem_u32(const void* p) {
    uint32_t a;
    asm("{ .reg .u64 t; cvta.to.shared.u64 t, %1; cvt.u32.u64 %0, t; }" : "=r"(a) : "l"(p));
    return a;
}

__device__ __forceinline__ void cp_async16(uint32_t dst, const void* src) {
    asm volatile("cp.async.cg.shared.global [%0], [%1], 16;" :: "r"(dst), "l"(src));
}
#define CP_COMMIT() asm volatile("cp.async.commit_group;" ::: "memory")
#define CP_WAIT1()  asm volatile("cp.async.wait_group 1;" ::: "memory")

__device__ __forceinline__ void ldsm_x4(uint32_t* r, uint32_t addr) {
    asm volatile("ldmatrix.sync.aligned.m8n8.x4.shared.b16 {%0,%1,%2,%3}, [%4];"
                 : "=r"(r[0]), "=r"(r[1]), "=r"(r[2]), "=r"(r[3]) : "r"(addr));
}

__device__ __forceinline__ void mma_f16(float* c, const uint32_t* a, const uint32_t* b) {
    asm volatile(
        "mma.sync.aligned.m16n8k16.row.col.f32.f16.f16.f32 "
        "{%0,%1,%2,%3}, {%4,%5,%6,%7}, {%8,%9}, {%0,%1,%2,%3};"
        : "+f"(c[0]), "+f"(c[1]), "+f"(c[2]), "+f"(c[3])
        : "r"(a[0]), "r"(a[1]), "r"(a[2]), "r"(a[3]),
          "r"(b[0]), "r"(b[1]));
}

// ---------------- edge preprocessing ----------------
__global__ void zero_kernel() {
    int i = blockIdx.x * blockDim.x + threadIdx.x;
    if (i < GM) { g_deg[i] = 0; g_cur[i] = 0; }
}

__global__ void hist_kernel(const int* __restrict__ dst) {
    int e = blockIdx.x * blockDim.x + threadIdx.x;
    if (e < GE) atomicAdd(&g_deg[dst[e]], 1);
}

__global__ void scan_kernel() {
    __shared__ int sh[1024];
    const int t = threadIdx.x;
    const int CH = 49;
    int base = t * CH;
    int s = 0;
    #pragma unroll 7
    for (int i = 0; i < CH; i++) {
        int idx = base + i;
        if (idx < GM) s += g_deg[idx];
    }
    sh[t] = s;
    __syncthreads();
    for (int off = 1; off < 1024; off <<= 1) {
        int v = 0;
        if (t >= off) v = sh[t - off];
        __syncthreads();
        if (t >= off) sh[t] += v;
        __syncthreads();
    }
    int run = (t == 0) ? 0 : sh[t - 1];
    for (int i = 0; i < CH; i++) {
        int idx = base + i;
        if (idx < GM) { g_off[idx] = run; run += g_deg[idx]; }
    }
    if (t == 1023) g_off[GM] = sh[1023];
}

__global__ void bucket_kernel(const int* __restrict__ src,
                              const int* __restrict__ dst,
                              const float* __restrict__ w) {
    int e = blockIdx.x * blockDim.x + threadIdx.x;
    if (e < GE) {
        int d = dst[e];
        int r = atomicAdd(&g_cur[d], 1);
        int p = g_off[d] + r;
        g_ssrc[p] = src[e];
        g_sw[p]   = w[e];
    }
}

// ---------------- fp16 conversions ----------------
// X -> g_Xh[m][kk] padded to GKP. grid (29, GM), block 128: 29*128 = 3712.
__global__ void xconv_kernel(const float* __restrict__ x) {
    const int kk = blockIdx.x * 128 + threadIdx.x;
    const int m  = blockIdx.y;
    float v = (kk < GK) ? x[(size_t)m * GK + kk] : 0.f;
    g_Xh[(size_t)m * GKP + kk] = __float2half(v);
}

// W1[k][n] -> g_W1th[n][kk] fp16, padded.
__global__ void wconv_kernel(const float* __restrict__ W1) {
    __shared__ float tile[32][33];
    const int k0 = blockIdx.x * 32;     // 116 blocks
    const int n0 = blockIdx.y * 32;     // 8 blocks
    const int tx = threadIdx.x, ty = threadIdx.y;   // 32 x 8
    #pragma unroll
    for (int i = 0; i < 4; i++) {
        int k = k0 + ty + i * 8;
        tile[ty + i * 8][tx] = (k < GK) ? W1[(size_t)k * GN + n0 + tx] : 0.f;
    }
    __syncthreads();
    #pragma unroll
    for (int i = 0; i < 4; i++) {
        int n = n0 + ty + i * 8;
        g_W1th[(size_t)n * GKP + k0 + tx] = __float2half(tile[tx][ty + i * 8]);
    }
}

// ---------------- GEMM1: support1 = fp16(X) @ fp16(W1), fp32 accumulate ----------------
// CTA tile 128x128, BK=32, 8 warps (2M x 4N), warp tile 64x32, m16n8k16 fp16 MMA.
// 3-stage cp.async pipeline, 1 __syncthreads per chunk, ldmatrix fragment loads.
// Smem per stage: A 128 rows x 80B, B 128 rows x 80B (padded rows: conflict-free ldmatrix).

__device__ __forceinline__ void issue_chunk(int m0, int n0, int kb,
                                            uint32_t stageBase, int tid) {
    const int k0 = kb * BK;
    #pragma unroll
    for (int j = 0; j < 2; j++) {           // A: 512 x 16B chunks, 2/thread
        int c = tid * 2 + j;
        int m = c >> 2, q = c & 3;
        int gm = m0 + m; if (gm >= GM) gm = GM - 1;   // clamp; results discarded at store
        cp_async16(stageBase + m * ROWB + q * 16,
                   g_Xh + (size_t)gm * GKP + k0 + q * 8);
    }
    #pragma unroll
    for (int j = 0; j < 2; j++) {           // B
        int c = tid * 2 + j;
        int n = c >> 2, q = c & 3;
        cp_async16(stageBase + 10240 + n * ROWB + q * 16,
                   g_W1th + (size_t)(n0 + n) * GKP + k0 + q * 8);
    }
}

__global__ __launch_bounds__(256, 2)
void gemm1_kernel() {
    extern __shared__ char smem[];
    const uint32_t sbase = smem_u32(smem);
    const int tid  = threadIdx.x;
    const int wid  = tid >> 5;
    const int lane = tid & 31;
    const int wr   = wid & 1;          // warp M (0..1) -> 64 rows
    const int wc   = wid >> 1;         // warp N (0..3) -> 32 cols
    const int m0   = blockIdx.y * 128;
    const int n0   = blockIdx.x * 128;

    // lane-dependent ldmatrix base offsets (bytes within a stage)
    // A: lanes 0-7 m0-7 k0 | 8-15 m8-15 k0 | 16-23 m0-7 k8 | 24-31 m8-15 k8
    const uint32_t aOff = (uint32_t)((wr * 64 + (lane & 15)) * ROWB + ((lane >> 4) * 8) * 2);
    // B: lanes 0-7 n0-7 k0 | 8-15 n0-7 k8 | 16-23 n8-15 k0 | 24-31 n8-15 k8
    const uint32_t bOff = 10240u +
        (uint32_t)((wc * 32 + ((lane >> 4) << 3) + (lane & 7)) * ROWB + (((lane >> 3) & 1) * 8) * 2);

    float acc[4][4][4];
    #pragma unroll
    for (int a = 0; a < 4; a++)
        #pragma unroll
        for (int b = 0; b < 4; b++)
            #pragma unroll
            for (int i = 0; i < 4; i++) acc[a][b][i] = 0.f;

    // prologue: chunks 0,1
    issue_chunk(m0, n0, 0, sbase + 0 * STAGE_BYTES, tid); CP_COMMIT();
    issue_chunk(m0, n0, 1, sbase + 1 * STAGE_BYTES, tid); CP_COMMIT();

    int stage = 0;          // stage of chunk kb
    int nextStage = 2;      // stage for chunk kb+2
    for (int kb = 0; kb < NCH; kb++) {
        CP_WAIT1();                       // chunk kb resident (per-thread)
        __syncthreads();                  // all threads' data visible; prev compute done

        if (kb + 2 < NCH) {
            issue_chunk(m0, n0, kb + 2, sbase + nextStage * STAGE_BYTES, tid);
        }
        CP_COMMIT();                      // commit (possibly empty) keeps group counting uniform

        const uint32_t sb = sbase + stage * STAGE_BYTES;
        #pragma unroll
        for (int ks = 0; ks < 2; ks++) {  // two k16 steps; +32B per step
            uint32_t af[4][4];
            #pragma unroll
            for (int mi = 0; mi < 4; mi++)
                ldsm_x4(af[mi], sb + aOff + mi * (16 * ROWB) + ks * 32);
            uint32_t bf[2][4];
            #pragma unroll
            for (int njp = 0; njp < 2; njp++)
                ldsm_x4(bf[njp], sb + bOff + njp * (16 * ROWB) + ks * 32);
            #pragma unroll
            for (int mi = 0; mi < 4; mi++) {
                #pragma unroll
                for (int nj = 0; nj < 4; nj++) {
                    const uint32_t* bp = &bf[nj >> 1][(nj & 1) * 2];
                    mma_f16(acc[mi][nj], af[mi], bp);
                }
            }
        }

        stage = (stage + 1 == NSTAGE) ? 0 : stage + 1;
        nextStage = (nextStage + 1 == NSTAGE) ? 0 : nextStage + 1;
    }

    // epilogue: acc -> g_support1
    const int rbase = m0 + wr * 64 + (lane >> 2);
    const int cbase = n0 + wc * 32 + (lane & 3) * 2;
    #pragma unroll
    for (int mi = 0; mi < 4; mi++) {
        const int r_lo = rbase + mi * 16;
        const int r_hi = r_lo + 8;
        #pragma unroll
        for (int nj = 0; nj < 4; nj++) {
            const int col = cbase + nj * 8;
            if (r_lo < GM) {
                float2 v; v.x = acc[mi][nj][0]; v.y = acc[mi][nj][1];
                *reinterpret_cast<float2*>(&g_support1[(size_t)r_lo * GN + col]) = v;
            }
            if (r_hi < GM) {
                float2 v; v.x = acc[mi][nj][2]; v.y = acc[mi][nj][3];
                *reinterpret_cast<float2*>(&g_support1[(size_t)r_hi * GN + col]) = v;
            }
        }
    }
}

// ---------------- layer-1 aggregation fused with +b1, leaky_relu, @W2 ----------------
__global__ __launch_bounds__(256)
void agg1_kernel(const float* __restrict__ b1, const float* __restrict__ W2) {
    __shared__ float sW2[GN * GO];
    __shared__ float sb1[GN];
    const int t = threadIdx.x;
    for (int i = t; i < GN * GO; i += 256) sW2[i] = W2[i];
    if (t < GN) sb1[t] = b1[t];
    __syncthreads();

    const int lane = t & 31;
    const int sub  = t >> 5;
    const int v    = blockIdx.x * 8 + sub;

    float4 a0 = make_float4(0.f, 0.f, 0.f, 0.f);
    float4 a1 = make_float4(0.f, 0.f, 0.f, 0.f);
    const int beg = g_off[v], end = g_off[v + 1];
    for (int e = beg; e < end; e++) {
        int s = g_ssrc[e];
        float w = g_sw[e];
        const float4* row = reinterpret_cast<const float4*>(g_support1 + (size_t)s * GN);
        float4 p0 = row[lane * 2];
        float4 p1 = row[lane * 2 + 1];
        a0.x += p0.x * w; a0.y += p0.y * w; a0.z += p0.z * w; a0.w += p0.w * w;
        a1.x += p1.x * w; a1.y += p1.y * w; a1.z += p1.z * w; a1.w += p1.w * w;
    }

    const int cb = lane * 8;
    float h[8];
    h[0] = a0.x + sb1[cb + 0]; h[1] = a0.y + sb1[cb + 1];
    h[2] = a0.z + sb1[cb + 2]; h[3] = a0.w + sb1[cb + 3];
    h[4] = a1.x + sb1[cb + 4]; h[5] = a1.y + sb1[cb + 5];
    h[6] = a1.z + sb1[cb + 6]; h[7] = a1.w + sb1[cb + 7];
    #pragma unroll
    for (int i = 0; i < 8; i++) h[i] = (h[i] > 0.f) ? h[i] : 0.01f * h[i];

    float p[GO];
    #pragma unroll
    for (int j = 0; j < GO; j++) p[j] = 0.f;
    #pragma unroll
    for (int i = 0; i < 8; i++) {
        const float* wr2 = &sW2[(cb + i) * GO];
        #pragma unroll
        for (int j = 0; j < GO; j++) p[j] += h[i] * wr2[j];
    }
    #pragma unroll
    for (int j = 0; j < GO; j++)
        #pragma unroll
        for (int o = 16; o > 0; o >>= 1)
            p[j] += __shfl_xor_sync(0xffffffffu, p[j], o);

    if (lane < GO) g_support2[(size_t)v * GO + lane] = p[lane];
}

// ---------------- layer-2 aggregation + b2 + log_softmax ----------------
__global__ void agg2_kernel(const float* __restrict__ b2, float* __restrict__ out) {
    int v = blockIdx.x * blockDim.x + threadIdx.x;
    if (v >= GM) return;
    float a[GO];
    #pragma unroll
    for (int j = 0; j < GO; j++) a[j] = 0.f;
    const int beg = g_off[v], end = g_off[v + 1];
    for (int e = beg; e < end; e++) {
        int s = g_ssrc[e];
        float w = g_sw[e];
        const float* r = g_support2 + (size_t)s * GO;
        #pragma unroll
        for (int j = 0; j < GO; j++) a[j] += __ldg(r + j) * w;
    }
    float l[GO];
    #pragma unroll
    for (int j = 0; j < GO; j++) l[j] = a[j] + b2[j];
    float m = l[0];
    #pragma unroll
    for (int j = 1; j < GO; j++) m = fmaxf(m, l[j]);
    float sum = 0.f;
    #pragma unroll
    for (int j = 0; j < GO; j++) sum += expf(l[j] - m);
    float ls = logf(sum);
    #pragma unroll
    for (int j = 0; j < GO; j++) out[(size_t)v * GO + j] = l[j] - m - ls;
}

// ---------------- launch ----------------
extern "C" void kernel_launch(void* const* d_in, const int* in_sizes, int n_in,
                              void* d_out, int out_size) {
    const float* x    = (const float*)d_in[0];
    const int*   esrc = (const int*)  d_in[1];
    const int*   edst = (const int*)  d_in[2];
    const float* ew   = (const float*)d_in[3];
    const float* W1   = (const float*)d_in[4];
    const float* b1   = (const float*)d_in[5];
    const float* W2   = (const float*)d_in[6];
    const float* b2   = (const float*)d_in[7];
    float* out = (float*)d_out;

    // edge preprocessing (counting sort by dst)
    zero_kernel  <<<(GM + 255) / 256, 256>>>();
    hist_kernel  <<<(GE + 255) / 256, 256>>>(edst);
    scan_kernel  <<<1, 1024>>>();
    bucket_kernel<<<(GE + 255) / 256, 256>>>(esrc, edst, ew);

    // fp16 conversions (padded K-major operands)
    xconv_kernel<<<dim3(29, GM), 128>>>(x);
    wconv_kernel<<<dim3(GKP / 32, GN / 32), dim3(32, 8)>>>(W1);

    // dense transform: fp16 tensor-core GEMM
    static bool attr_set = false;
    if (!attr_set) {
        cudaFuncSetAttribute(gemm1_kernel,
                             cudaFuncAttributeMaxDynamicSharedMemorySize,
                             NSTAGE * STAGE_BYTES);
        attr_set = true;
    }
    gemm1_kernel<<<dim3(2, (GM + 127) / 128), 256, NSTAGE * STAGE_BYTES>>>();

    // sparse agg 1 (+b1, leaky_relu, @W2 fused)
    agg1_kernel<<<GM / 8, 256>>>(b1, W2);

    // sparse agg 2 (+b2, log_softmax)
    agg2_kernel<<<(GM + 127) / 128, 128>>>(b2, out);
}

// round 8
// speedup vs baseline: 2.4657x; 2.4657x over previous
#include <cuda_runtime.h>
#include <cuda_fp16.h>
#include <math.h>
#include <cstdint>

// Problem constants (fixed by the reference)
#define GM 50000        // nodes
#define GK 3703         // input dim
#define GKP 3712        // padded K (multiple of 32; rows 16B aligned in fp16)
#define GN 256          // hidden dim
#define GE 400000       // edges
#define GO 6            // output classes

#define BK 32           // K per chunk (fp16)
#define NCH (GKP / BK)  // 116
#define ROWB 80         // padded smem row stride in bytes (32 halves -> 40 halves)
#define STAGE_BYTES 20480   // A(128*80) + B(128*80)
#define NSTAGE 4

// ---------------- scratch (static device memory; no allocation) ----------------
__device__ __align__(16) float  g_support1[(size_t)GM * GN];  // X @ W1    (51.2 MB)
__device__ __align__(16) float  g_support2[(size_t)GM * GO];  // h1 @ W2   (1.2 MB)
__device__ __align__(16) __half g_Xh[(size_t)GM * GKP];       // fp16 X, padded (371 MB)
__device__ __align__(16) __half g_W1th[(size_t)GN * GKP];     // fp16 W1^T, padded (1.9 MB)
__device__ int   g_deg[GM];
__device__ int   g_cur[GM];
__device__ int   g_off[GM + 1];
__device__ int   g_ssrc[GE];
__device__ float g_sw[GE];

// ---------------- ptx helpers ----------------
__device__ __forceinline__ uint32_t smem_u32(const void* p) {
    uint32_t a;
    asm("{ .reg .u64 t; cvta.to.shared.u64 t, %1; cvt.u32.u64 %0, t; }" : "=r"(a) : "l"(p));
    return a;
}

__device__ __forceinline__ void cp_async16(uint32_t dst, const void* src) {
    asm volatile("cp.async.cg.shared.global [%0], [%1], 16;" :: "r"(dst), "l"(src));
}
#define CP_COMMIT() asm volatile("cp.async.commit_group;" ::: "memory")
#define CP_WAIT2()  asm volatile("cp.async.wait_group 2;" ::: "memory")

__device__ __forceinline__ void ldsm_x4(uint32_t* r, uint32_t addr) {
    asm volatile("ldmatrix.sync.aligned.m8n8.x4.shared.b16 {%0,%1,%2,%3}, [%4];"
                 : "=r"(r[0]), "=r"(r[1]), "=r"(r[2]), "=r"(r[3]) : "r"(addr));
}

__device__ __forceinline__ void mma_f16(float* c, const uint32_t* a, const uint32_t* b) {
    asm volatile(
        "mma.sync.aligned.m16n8k16.row.col.f32.f16.f16.f32 "
        "{%0,%1,%2,%3}, {%4,%5,%6,%7}, {%8,%9}, {%0,%1,%2,%3};"
        : "+f"(c[0]), "+f"(c[1]), "+f"(c[2]), "+f"(c[3])
        : "r"(a[0]), "r"(a[1]), "r"(a[2]), "r"(a[3]),
          "r"(b[0]), "r"(b[1]));
}

// ---------------- edge preprocessing ----------------
__global__ void zero_kernel() {
    int i = blockIdx.x * blockDim.x + threadIdx.x;
    if (i < GM) { g_deg[i] = 0; g_cur[i] = 0; }
}

__global__ void hist_kernel(const int* __restrict__ dst) {
    int e = blockIdx.x * blockDim.x + threadIdx.x;
    if (e < GE) atomicAdd(&g_deg[dst[e]], 1);
}

__global__ void scan_kernel() {
    __shared__ int sh[1024];
    const int t = threadIdx.x;
    const int CH = 49;
    int base = t * CH;
    int s = 0;
    #pragma unroll 7
    for (int i = 0; i < CH; i++) {
        int idx = base + i;
        if (idx < GM) s += g_deg[idx];
    }
    sh[t] = s;
    __syncthreads();
    for (int off = 1; off < 1024; off <<= 1) {
        int v = 0;
        if (t >= off) v = sh[t - off];
        __syncthreads();
        if (t >= off) sh[t] += v;
        __syncthreads();
    }
    int run = (t == 0) ? 0 : sh[t - 1];
    for (int i = 0; i < CH; i++) {
        int idx = base + i;
        if (idx < GM) { g_off[idx] = run; run += g_deg[idx]; }
    }
    if (t == 1023) g_off[GM] = sh[1023];
}

__global__ void bucket_kernel(const int* __restrict__ src,
                              const int* __restrict__ dst,
                              const float* __restrict__ w) {
    int e = blockIdx.x * blockDim.x + threadIdx.x;
    if (e < GE) {
        int d = dst[e];
        int r = atomicAdd(&g_cur[d], 1);
        int p = g_off[d] + r;
        g_ssrc[p] = src[e];
        g_sw[p]   = w[e];
    }
}

// ---------------- fp16 conversions ----------------
// One CTA per row; half2 packed stores, coalesced. 50k CTAs (was 1.45M).
__global__ __launch_bounds__(256)
void xconv_kernel(const float* __restrict__ x) {
    const int m = blockIdx.x;
    const float* xr = x + (size_t)m * GK;
    __half2* orow = reinterpret_cast<__half2*>(g_Xh + (size_t)m * GKP);
    #pragma unroll
    for (int i = threadIdx.x; i < GKP / 2; i += 256) {
        const int k = 2 * i;
        float a = (k < GK) ? __ldg(xr + k) : 0.f;
        float b = (k + 1 < GK) ? __ldg(xr + k + 1) : 0.f;
        orow[i] = __floats2half2_rn(a, b);
    }
}

// W1[k][n] -> g_W1th[n][kk] fp16, padded.
__global__ void wconv_kernel(const float* __restrict__ W1) {
    __shared__ float tile[32][33];
    const int k0 = blockIdx.x * 32;     // 116 blocks
    const int n0 = blockIdx.y * 32;     // 8 blocks
    const int tx = threadIdx.x, ty = threadIdx.y;   // 32 x 8
    #pragma unroll
    for (int i = 0; i < 4; i++) {
        int k = k0 + ty + i * 8;
        tile[ty + i * 8][tx] = (k < GK) ? W1[(size_t)k * GN + n0 + tx] : 0.f;
    }
    __syncthreads();
    #pragma unroll
    for (int i = 0; i < 4; i++) {
        int n = n0 + ty + i * 8;
        g_W1th[(size_t)n * GKP + k0 + tx] = __float2half(tile[tx][ty + i * 8]);
    }
}

// ---------------- GEMM1: support1 = fp16(X) @ fp16(W1), fp32 accumulate ----------------
// CTA tile 128x128, BK=32, 8 warps (2M x 4N), warp tile 64x32, m16n8k16 fp16 MMA.
// 4-stage cp.async pipeline (prefetch distance 3), 1 __syncthreads per chunk,
// ldmatrix fragment loads. Stage: A 128x80B + B 128x80B (padded rows: conflict-free).

__device__ __forceinline__ void issue_chunk(int m0, int n0, int kb,
                                            uint32_t stageBase, int tid) {
    const int k0 = kb * BK;
    #pragma unroll
    for (int j = 0; j < 2; j++) {           // A: 512 x 16B chunks, 2/thread
        int c = tid * 2 + j;
        int m = c >> 2, q = c & 3;
        int gm = m0 + m; if (gm >= GM) gm = GM - 1;   // clamp; results discarded at store
        cp_async16(stageBase + m * ROWB + q * 16,
                   g_Xh + (size_t)gm * GKP + k0 + q * 8);
    }
    #pragma unroll
    for (int j = 0; j < 2; j++) {           // B
        int c = tid * 2 + j;
        int n = c >> 2, q = c & 3;
        cp_async16(stageBase + 10240 + n * ROWB + q * 16,
                   g_W1th + (size_t)(n0 + n) * GKP + k0 + q * 8);
    }
}

__global__ __launch_bounds__(256, 2)
void gemm1_kernel() {
    extern __shared__ char smem[];
    const uint32_t sbase = smem_u32(smem);
    const int tid  = threadIdx.x;
    const int wid  = tid >> 5;
    const int lane = tid & 31;
    const int wr   = wid & 1;          // warp M (0..1) -> 64 rows
    const int wc   = wid >> 1;         // warp N (0..3) -> 32 cols
    const int m0   = blockIdx.y * 128;
    const int n0   = blockIdx.x * 128;

    // lane-dependent ldmatrix base offsets (bytes within a stage)
    const uint32_t aOff = (uint32_t)((wr * 64 + (lane & 15)) * ROWB + ((lane >> 4) * 8) * 2);
    const uint32_t bOff = 10240u +
        (uint32_t)((wc * 32 + ((lane >> 4) << 3) + (lane & 7)) * ROWB + (((lane >> 3) & 1) * 8) * 2);

    float acc[4][4][4];
    #pragma unroll
    for (int a = 0; a < 4; a++)
        #pragma unroll
        for (int b = 0; b < 4; b++)
            #pragma unroll
            for (int i = 0; i < 4; i++) acc[a][b][i] = 0.f;

    // prologue: chunks 0,1,2
    issue_chunk(m0, n0, 0, sbase + 0 * STAGE_BYTES, tid); CP_COMMIT();
    issue_chunk(m0, n0, 1, sbase + 1 * STAGE_BYTES, tid); CP_COMMIT();
    issue_chunk(m0, n0, 2, sbase + 2 * STAGE_BYTES, tid); CP_COMMIT();

    for (int kb = 0; kb < NCH; kb++) {
        // Positional invariant: exactly 2 groups are newer than chunk kb's group
        // (one group committed per iteration, empty or not), so wait_group 2
        // guarantees chunk kb is resident.
        CP_WAIT2();
        __syncthreads();                  // all threads' data visible; prev compute done

        if (kb + 3 < NCH) {
            issue_chunk(m0, n0, kb + 3, sbase + ((kb + 3) & 3) * STAGE_BYTES, tid);
        }
        CP_COMMIT();                      // one group per iteration, keeps counting uniform

        const uint32_t sb = sbase + (kb & 3) * STAGE_BYTES;
        #pragma unroll
        for (int ks = 0; ks < 2; ks++) {  // two k16 steps; +32B per step
            uint32_t af[4][4];
            #pragma unroll
            for (int mi = 0; mi < 4; mi++)
                ldsm_x4(af[mi], sb + aOff + mi * (16 * ROWB) + ks * 32);
            uint32_t bf[2][4];
            #pragma unroll
            for (int njp = 0; njp < 2; njp++)
                ldsm_x4(bf[njp], sb + bOff + njp * (16 * ROWB) + ks * 32);
            #pragma unroll
            for (int mi = 0; mi < 4; mi++) {
                #pragma unroll
                for (int nj = 0; nj < 4; nj++) {
                    const uint32_t* bp = &bf[nj >> 1][(nj & 1) * 2];
                    mma_f16(acc[mi][nj], af[mi], bp);
                }
            }
        }
    }

    // epilogue: acc -> g_support1
    const int rbase = m0 + wr * 64 + (lane >> 2);
    const int cbase = n0 + wc * 32 + (lane & 3) * 2;
    #pragma unroll
    for (int mi = 0; mi < 4; mi++) {
        const int r_lo = rbase + mi * 16;
        const int r_hi = r_lo + 8;
        #pragma unroll
        for (int nj = 0; nj < 4; nj++) {
            const int col = cbase + nj * 8;
            if (r_lo < GM) {
                float2 v; v.x = acc[mi][nj][0]; v.y = acc[mi][nj][1];
                *reinterpret_cast<float2*>(&g_support1[(size_t)r_lo * GN + col]) = v;
            }
            if (r_hi < GM) {
                float2 v; v.x = acc[mi][nj][2]; v.y = acc[mi][nj][3];
                *reinterpret_cast<float2*>(&g_support1[(size_t)r_hi * GN + col]) = v;
            }
        }
    }
}

// ---------------- layer-1 aggregation fused with +b1, leaky_relu, @W2 ----------------
__global__ __launch_bounds__(256)
void agg1_kernel(const float* __restrict__ b1, const float* __restrict__ W2) {
    __shared__ float sW2[GN * GO];
    __shared__ float sb1[GN];
    const int t = threadIdx.x;
    for (int i = t; i < GN * GO; i += 256) sW2[i] = W2[i];
    if (t < GN) sb1[t] = b1[t];
    __syncthreads();

    const int lane = t & 31;
    const int sub  = t >> 5;
    const int v    = blockIdx.x * 8 + sub;

    float4 a0 = make_float4(0.f, 0.f, 0.f, 0.f);
    float4 a1 = make_float4(0.f, 0.f, 0.f, 0.f);
    const int beg = g_off[v], end = g_off[v + 1];
    for (int e = beg; e < end; e++) {
        int s = g_ssrc[e];
        float w = g_sw[e];
        const float4* row = reinterpret_cast<const float4*>(g_support1 + (size_t)s * GN);
        float4 p0 = row[lane * 2];
        float4 p1 = row[lane * 2 + 1];
        a0.x += p0.x * w; a0.y += p0.y * w; a0.z += p0.z * w; a0.w += p0.w * w;
        a1.x += p1.x * w; a1.y += p1.y * w; a1.z += p1.z * w; a1.w += p1.w * w;
    }

    const int cb = lane * 8;
    float h[8];
    h[0] = a0.x + sb1[cb + 0]; h[1] = a0.y + sb1[cb + 1];
    h[2] = a0.z + sb1[cb + 2]; h[3] = a0.w + sb1[cb + 3];
    h[4] = a1.x + sb1[cb + 4]; h[5] = a1.y + sb1[cb + 5];
    h[6] = a1.z + sb1[cb + 6]; h[7] = a1.w + sb1[cb + 7];
    #pragma unroll
    for (int i = 0; i < 8; i++) h[i] = (h[i] > 0.f) ? h[i] : 0.01f * h[i];

    float p[GO];
    #pragma unroll
    for (int j = 0; j < GO; j++) p[j] = 0.f;
    #pragma unroll
    for (int i = 0; i < 8; i++) {
        const float* wr2 = &sW2[(cb + i) * GO];
        #pragma unroll
        for (int j = 0; j < GO; j++) p[j] += h[i] * wr2[j];
    }
    #pragma unroll
    for (int j = 0; j < GO; j++)
        #pragma unroll
        for (int o = 16; o > 0; o >>= 1)
            p[j] += __shfl_xor_sync(0xffffffffu, p[j], o);

    if (lane < GO) g_support2[(size_t)v * GO + lane] = p[lane];
}

// ---------------- layer-2 aggregation + b2 + log_softmax ----------------
__global__ void agg2_kernel(const float* __restrict__ b2, float* __restrict__ out) {
    int v = blockIdx.x * blockDim.x + threadIdx.x;
    if (v >= GM) return;
    float a[GO];
    #pragma unroll
    for (int j = 0; j < GO; j++) a[j] = 0.f;
    const int beg = g_off[v], end = g_off[v + 1];
    for (int e = beg; e < end; e++) {
        int s = g_ssrc[e];
        float w = g_sw[e];
        const float* r = g_support2 + (size_t)s * GO;
        #pragma unroll
        for (int j = 0; j < GO; j++) a[j] += __ldg(r + j) * w;
    }
    float l[GO];
    #pragma unroll
    for (int j = 0; j < GO; j++) l[j] = a[j] + b2[j];
    float m = l[0];
    #pragma unroll
    for (int j = 1; j < GO; j++) m = fmaxf(m, l[j]);
    float sum = 0.f;
    #pragma unroll
    for (int j = 0; j < GO; j++) sum += expf(l[j] - m);
    float ls = logf(sum);
    #pragma unroll
    for (int j = 0; j < GO; j++) out[(size_t)v * GO + j] = l[j] - m - ls;
}

// ---------------- launch ----------------
extern "C" void kernel_launch(void* const* d_in, const int* in_sizes, int n_in,
                              void* d_out, int out_size) {
    const float* x    = (const float*)d_in[0];
    const int*   esrc = (const int*)  d_in[1];
    const int*   edst = (const int*)  d_in[2];
    const float* ew   = (const float*)d_in[3];
    const float* W1   = (const float*)d_in[4];
    const float* b1   = (const float*)d_in[5];
    const float* W2   = (const float*)d_in[6];
    const float* b2   = (const float*)d_in[7];
    float* out = (float*)d_out;

    // edge preprocessing (counting sort by dst)
    zero_kernel  <<<(GM + 255) / 256, 256>>>();
    hist_kernel  <<<(GE + 255) / 256, 256>>>(edst);
    scan_kernel  <<<1, 1024>>>();
    bucket_kernel<<<(GE + 255) / 256, 256>>>(esrc, edst, ew);

    // fp16 conversions (padded K-major operands)
    xconv_kernel<<<GM, 256>>>(x);
    wconv_kernel<<<dim3(GKP / 32, GN / 32), dim3(32, 8)>>>(W1);

    // dense transform: fp16 tensor-core GEMM, 4-stage cp.async pipeline
    cudaFuncSetAttribute(gemm1_kernel,
                         cudaFuncAttributeMaxDynamicSharedMemorySize,
                         NSTAGE * STAGE_BYTES);
    gemm1_kernel<<<dim3(2, (GM + 127) / 128), 256, NSTAGE * STAGE_BYTES>>>();

    // sparse agg 1 (+b1, leaky_relu, @W2 fused)
    agg1_kernel<<<GM / 8, 256>>>(b1, W2);

    // sparse agg 2 (+b2, log_softmax)
    agg2_kernel<<<(GM + 127) / 128, 128>>>(b2, out);
}